// round 4
// baseline (speedup 1.0000x reference)
#include <cuda_runtime.h>
#include <cuda_bf16.h>

// Problem constants (fixed shapes from reference setup_inputs)
#define BB 2048
#define NN 8192
#define LL 512
#define NEGBIG (-1e30f)
#define TPB 256
#define EPT 2           // elements (of L) per thread
#define NWARP (TPB/32)

// Per-row scratch + completion counter (allocation-free: __device__ globals)
__device__ float        g_row_ll[BB];
__device__ unsigned     g_row_used[BB];
__device__ unsigned int g_done_count = 0;   // returns to 0 at end of every launch

// One block (256 threads) per row. Stream the whole 32KB row into smem
// (coalesced float4 -> near-peak DRAM BW), gather from smem, then
// suffix-logsumexp scan. Last-arriving block does the final reduction.
__global__ __launch_bounds__(TPB) void listnet_fused_kernel(
    const float* __restrict__ s, const int* __restrict__ seqs,
    float* __restrict__ out)
{
    __shared__ float srow[NN];              // 32 KB
    __shared__ float smax[NWARP];
    __shared__ float swsum[NWARP];
    __shared__ float sll[NWARP];
    __shared__ unsigned sany[NWARP];
    __shared__ unsigned is_last;

    const int b    = blockIdx.x;
    const int t    = threadIdx.x;
    const int lane = t & 31;
    const int warp = t >> 5;

    // ---- coalesced streaming load of the full row into smem ----
    const float4* __restrict__ srow4 = (const float4*)(s + (size_t)b * NN);
    float4*       dsm4               = (float4*)srow;
#pragma unroll
    for (int i = 0; i < (NN / 4) / TPB; i++) {      // 8 float4 per thread
        dsm4[t + i * TPB] = srow4[t + i * TPB];
    }

    // ---- coalesced load of this thread's 2 indices ----
    const int2 vi = *(const int2*)(seqs + (size_t)b * LL + t * EPT);
    int v[EPT] = {vi.x, vi.y};

    __syncthreads();                                 // row visible in smem

    // ---- gather from smem + sanitize ----
    float g[EPT], e[EPT];
    bool  mk[EPT];
#pragma unroll
    for (int j = 0; j < EPT; j++) {
        int vv = v[j];
        mk[j] = (vv != -1);
        int idx = vv < 0 ? 0 : (vv > (NN - 1) ? (NN - 1) : vv);
        float x = srow[idx];
        // sanitize: inf -> +/-1e6 via clamp, nan -> 0
        x = fminf(fmaxf(x, -1e6f), 1e6f);
        x = (x != x) ? 0.0f : x;
        g[j] = x;
    }

    // ---- block max over valid entries ----
    float mx = NEGBIG;
#pragma unroll
    for (int j = 0; j < EPT; j++) mx = fmaxf(mx, mk[j] ? g[j] : NEGBIG);
#pragma unroll
    for (int off = 16; off; off >>= 1)
        mx = fmaxf(mx, __shfl_xor_sync(0xffffffffu, mx, off));
    if (lane == 0) smax[warp] = mx;
    __syncthreads();
    float M = NEGBIG;
#pragma unroll
    for (int w = 0; w < NWARP; w++) M = fmaxf(M, smax[w]);

    // ---- exp per valid element (masked -> 0) ----
#pragma unroll
    for (int j = 0; j < EPT; j++) e[j] = mk[j] ? __expf(g[j] - M) : 0.0f;

    // ---- suffix (reverse) sum scan of exp values across the block ----
    float csum = e[0] + e[1];                 // per-thread chunk total
    float incl = csum;                        // inclusive suffix within warp
#pragma unroll
    for (int off = 1; off < 32; off <<= 1) {
        float o = __shfl_down_sync(0xffffffffu, incl, off);
        if (lane + off < 32) incl += o;
    }
    if (lane == 0) swsum[warp] = incl;        // warp totals
    __syncthreads();
    float after = 0.0f;
#pragma unroll
    for (int w = 0; w < NWARP; w++) if (w > warp) after += swsum[w];
    float exclw = __shfl_down_sync(0xffffffffu, incl, 1);   // exclusive within warp
    float acc = ((lane < 31) ? exclw : 0.0f) + after;

    // ---- per-element log_den + masked NLL accumulation (right-to-left) ----
    float ll = 0.0f;
#pragma unroll
    for (int j = EPT - 1; j >= 0; j--) {
        acc += e[j];                                 // suffix sum incl. element j
        if (mk[j]) ll += g[j] - (M + __logf(acc));   // log_den = M + log(sum)
    }

    // ---- block reduce ll + "row used" flag ----
    bool any = mk[0] || mk[1];
    unsigned anyb = __ballot_sync(0xffffffffu, any);
#pragma unroll
    for (int off = 16; off; off >>= 1)
        ll += __shfl_xor_sync(0xffffffffu, ll, off);
    if (lane == 0) { sll[warp] = ll; sany[warp] = anyb; }
    __syncthreads();

    if (t == 0) {
        float rsum = 0.0f; unsigned ru = 0u;
#pragma unroll
        for (int w = 0; w < NWARP; w++) { rsum += sll[w]; ru |= sany[w]; }
        g_row_ll[b]   = rsum;
        g_row_used[b] = ru ? 1u : 0u;
        __threadfence();                           // publish row result
        unsigned prev = atomicAdd(&g_done_count, 1u);
        is_last = (prev == BB - 1) ? 1u : 0u;
    }
    __syncthreads();

    // ---- last block: deterministic final reduction over all rows ----
    if (is_last) {
        float sum = 0.0f;
        int   cnt = 0;
#pragma unroll
        for (int i = t; i < BB; i += TPB) {        // fixed order -> deterministic
            unsigned u = __ldcg(&g_row_used[i]);   // bypass L1 (same-launch writes)
            float    r = __ldcg(&g_row_ll[i]);
            if (u) { sum += r; cnt++; }
        }
#pragma unroll
        for (int off = 16; off; off >>= 1) {
            sum += __shfl_xor_sync(0xffffffffu, sum, off);
            cnt += __shfl_xor_sync(0xffffffffu, cnt, off);
        }
        __shared__ float fsum[NWARP];
        __shared__ int   fcnt[NWARP];
        if (lane == 0) { fsum[warp] = sum; fcnt[warp] = cnt; }
        __syncthreads();
        if (t == 0) {
            float S = 0.0f; int C = 0;
#pragma unroll
            for (int w = 0; w < NWARP; w++) { S += fsum[w]; C += fcnt[w]; }
            out[0] = (C > 0) ? (-S / (float)C) : 0.0f;
            g_done_count = 0;                      // reset for next graph replay
        }
    }
}

extern "C" void kernel_launch(void* const* d_in, const int* in_sizes, int n_in,
                              void* d_out, int out_size)
{
    const float* s    = (const float*)d_in[0];   // [B, N] float32
    const int*   seqs = (const int*)d_in[1];     // [B, L] int32 (JAX x64 off)
    float*       out  = (float*)d_out;           // [1] float32

    listnet_fused_kernel<<<BB, TPB>>>(s, seqs, out);
}

// round 5
// speedup vs baseline: 1.1969x; 1.1969x over previous
#include <cuda_runtime.h>
#include <cuda_bf16.h>

// Problem constants (fixed shapes from reference setup_inputs)
#define BB 2048
#define NN 8192
#define LL 512
#define NEGBIG (-1e30f)

// Scratch (allocation-free: __device__ globals)
__device__ float        g_gm[BB * LL];      // sanitized gathered scores; NEGBIG = masked
__device__ float        g_row_ll[BB];
__device__ unsigned     g_row_used[BB];
__device__ unsigned int g_done_count = 0;   // returns to 0 at end of every launch

// ---------------- K1: pure gather (latency-optimized, no syncs) ----------------
// 1M elements, 4 per thread. Coalesced int4 index load, 4 independent random
// gathers (L2-resident), fused sanitize + mask encode, coalesced float4 store.
__global__ __launch_bounds__(256) void gather_kernel(
    const float* __restrict__ s, const int* __restrict__ seqs)
{
    const int tid  = blockIdx.x * 256 + threadIdx.x;   // 0 .. 256K-1
    const int base = tid * 4;                           // element index in [B*L)

    const int4 vi = *(const int4*)(seqs + base);
    const int b   = base >> 9;                          // base / LL (LL=512)
    const float* __restrict__ srow = s + (size_t)b * NN;

    int v[4] = {vi.x, vi.y, vi.z, vi.w};
    float r[4];
#pragma unroll
    for (int j = 0; j < 4; j++) {
        int vv  = v[j];
        int idx = vv < 0 ? 0 : (vv > (NN - 1) ? (NN - 1) : vv);
        float x = __ldg(srow + idx);                    // random gather
        x = fminf(fmaxf(x, -1e6f), 1e6f);               // inf -> +/-1e6
        x = (x != x) ? 0.0f : x;                        // nan -> 0
        r[j] = (vv != -1) ? x : NEGBIG;                 // mask encode
    }
    *(float4*)(g_gm + base) = make_float4(r[0], r[1], r[2], r[3]);
}

// ---------------- K2: per-row suffix-logsumexp scan + final reduce ----------------
// One 128-thread block per row, 4 elements/thread, all loads coalesced.
__global__ __launch_bounds__(128) void scan_kernel(float* __restrict__ out)
{
    const int b    = blockIdx.x;
    const int t    = threadIdx.x;
    const int lane = t & 31;
    const int warp = t >> 5;

    // coalesced float4 load of 4 gm values (bypass L1: written by K1 this graph)
    const float4 gv = __ldcg((const float4*)(g_gm + (size_t)b * LL + t * 4));
    float gm[4] = {gv.x, gv.y, gv.z, gv.w};
    bool  mk[4];
#pragma unroll
    for (int j = 0; j < 4; j++) mk[j] = (gm[j] != NEGBIG);

    // ---- block max ----
    float mx = fmaxf(fmaxf(gm[0], gm[1]), fmaxf(gm[2], gm[3]));
#pragma unroll
    for (int off = 16; off; off >>= 1)
        mx = fmaxf(mx, __shfl_xor_sync(0xffffffffu, mx, off));
    __shared__ float smax[4];
    __shared__ float swsum[4];
    if (lane == 0) smax[warp] = mx;
    __syncthreads();
    const float M = fmaxf(fmaxf(smax[0], smax[1]), fmaxf(smax[2], smax[3]));

    // ---- exp per valid element (masked -> 0) ----
    float e[4];
#pragma unroll
    for (int j = 0; j < 4; j++) e[j] = mk[j] ? __expf(gm[j] - M) : 0.0f;

    // ---- suffix (reverse) sum scan across the block ----
    float csum = (e[0] + e[1]) + (e[2] + e[3]);
    float incl = csum;
#pragma unroll
    for (int off = 1; off < 32; off <<= 1) {
        float o = __shfl_down_sync(0xffffffffu, incl, off);
        if (lane + off < 32) incl += o;
    }
    if (lane == 0) swsum[warp] = incl;
    __syncthreads();
    float after = 0.0f;
    for (int w = warp + 1; w < 4; w++) after += swsum[w];
    float exclw = __shfl_down_sync(0xffffffffu, incl, 1);
    float acc = ((lane < 31) ? exclw : 0.0f) + after;

    // ---- per-element log_den + masked NLL (right-to-left) ----
    float ll = 0.0f;
#pragma unroll
    for (int j = 3; j >= 0; j--) {
        acc += e[j];
        if (mk[j]) ll += gm[j] - (M + __logf(acc));
    }

    // ---- block reduce ll + used flag ----
    bool any = mk[0] || mk[1] || mk[2] || mk[3];
    unsigned anyb = __ballot_sync(0xffffffffu, any);
#pragma unroll
    for (int off = 16; off; off >>= 1)
        ll += __shfl_xor_sync(0xffffffffu, ll, off);
    __shared__ float    sll[4];
    __shared__ unsigned sany[4];
    if (lane == 0) { sll[warp] = ll; sany[warp] = anyb; }
    __syncthreads();

    __shared__ unsigned is_last;
    if (t == 0) {
        g_row_ll[b]   = (sll[0] + sll[1]) + (sll[2] + sll[3]);
        g_row_used[b] = (sany[0] | sany[1] | sany[2] | sany[3]) ? 1u : 0u;
        __threadfence();
        unsigned prev = atomicAdd(&g_done_count, 1u);
        is_last = (prev == BB - 1) ? 1u : 0u;
    }
    __syncthreads();

    // ---- last block: deterministic final reduction ----
    if (is_last) {
        float sum = 0.0f;
        int   cnt = 0;
#pragma unroll
        for (int i = t; i < BB; i += 128) {
            unsigned u = __ldcg(&g_row_used[i]);
            float    r = __ldcg(&g_row_ll[i]);
            if (u) { sum += r; cnt++; }
        }
#pragma unroll
        for (int off = 16; off; off >>= 1) {
            sum += __shfl_xor_sync(0xffffffffu, sum, off);
            cnt += __shfl_xor_sync(0xffffffffu, cnt, off);
        }
        __shared__ float fsum[4];
        __shared__ int   fcnt[4];
        if (lane == 0) { fsum[warp] = sum; fcnt[warp] = cnt; }
        __syncthreads();
        if (t == 0) {
            float S = (fsum[0] + fsum[1]) + (fsum[2] + fsum[3]);
            int   C = (fcnt[0] + fcnt[1]) + (fcnt[2] + fcnt[3]);
            out[0] = (C > 0) ? (-S / (float)C) : 0.0f;
            g_done_count = 0;                      // reset for next graph replay
        }
    }
}

extern "C" void kernel_launch(void* const* d_in, const int* in_sizes, int n_in,
                              void* d_out, int out_size)
{
    const float* s    = (const float*)d_in[0];   // [B, N] float32
    const int*   seqs = (const int*)d_in[1];     // [B, L] int32 (JAX x64 off)
    float*       out  = (float*)d_out;           // [1] float32

    gather_kernel<<<(BB * LL) / (256 * 4), 256>>>(s, seqs);  // 1024 blocks
    scan_kernel<<<BB, 128>>>(out);
}

// round 6
// speedup vs baseline: 1.5418x; 1.2882x over previous
#include <cuda_runtime.h>
#include <cuda_bf16.h>

// Fixed shapes from reference setup_inputs
#define BB 2048
#define NN 8192
#define LL 512
#define NEGBIG (-1e30f)
#define TPB 256
#define WPB 8               // warps per block
#define GRID (BB / WPB)     // 256 blocks
#define EPL 16              // elements per lane (LL / 32)

// Scratch (allocation-free)
__device__ float    g_row_ll[BB];
__device__ unsigned g_row_used[BB];
__device__ unsigned g_done_count = 0;   // returns to 0 each launch

__global__ __launch_bounds__(TPB) void listnet_warp_kernel(
    const float* __restrict__ s, const int* __restrict__ seqs,
    float* __restrict__ out)
{
    const int t    = threadIdx.x;
    const int lane = t & 31;
    const int w    = t >> 5;
    const int row  = blockIdx.x * WPB + w;

    const float* __restrict__ srow = s + (size_t)row * NN;
    const int*   __restrict__ qrow = seqs + (size_t)row * LL + lane * EPL;

    // ---- load 16 indices (4x int4, 64B-aligned) ----
    int v[EPL];
#pragma unroll
    for (int c = 0; c < 4; c++) {
        int4 vi = *(const int4*)(qrow + c * 4);
        v[c * 4 + 0] = vi.x; v[c * 4 + 1] = vi.y;
        v[c * 4 + 2] = vi.z; v[c * 4 + 3] = vi.w;
    }

    // ---- predicated gathers + sanitize; g = gm (NEGBIG when masked) ----
    float    g[EPL];
    unsigned mkb = 0u;
#pragma unroll
    for (int j = 0; j < EPL; j++) {
        const int  vv = v[j];
        const bool mk = (vv != -1);
        float x = NEGBIG;
        if (mk) {                                   // predicated: no wavefronts for padding
            int idx = vv < 0 ? 0 : (vv > (NN - 1) ? (NN - 1) : vv);
            x = __ldg(srow + idx);
            x = fminf(fmaxf(x, -1e6f), 1e6f);       // inf -> +/-1e6
            x = (x != x) ? 0.0f : x;                // nan -> 0
        }
        g[j] = x;
        mkb |= (mk ? 1u : 0u) << j;
    }

    // ---- warp max (masked entries are NEGBIG) ----
    float mx = g[0];
#pragma unroll
    for (int j = 1; j < EPL; j++) mx = fmaxf(mx, g[j]);
#pragma unroll
    for (int off = 16; off; off >>= 1)
        mx = fmaxf(mx, __shfl_xor_sync(0xffffffffu, mx, off));
    const float M = mx;

    // ---- exp (masked -> exp(-huge) = 0 automatically) ----
    float e[EPL];
#pragma unroll
    for (int j = 0; j < EPL; j++) e[j] = __expf(g[j] - M);

    // ---- serial intra-lane suffix sum: e[j] := sum_{l>=j within lane} ----
#pragma unroll
    for (int j = EPL - 2; j >= 0; j--) e[j] += e[j + 1];
    const float T = e[0];                           // lane total

    // ---- warp inclusive-suffix scan of lane totals ----
    float incl = T;
#pragma unroll
    for (int off = 1; off < 32; off <<= 1) {
        float o = __shfl_down_sync(0xffffffffu, incl, off);
        if (lane + off < 32) incl += o;
    }
    float Aexcl = __shfl_down_sync(0xffffffffu, incl, 1);   // suffix of higher lanes
    if (lane == 31) Aexcl = 0.0f;

    // ---- batched logs: one __logf per 4-element chunk (log of product) ----
    // suffix_j = e[j] + Aexcl; term_j = g[j] - M - log(suffix_j)
    float ll = 0.0f;
#pragma unroll
    for (int c = 0; c < 4; c++) {
        float prod = 1.0f, gs = 0.0f;
        int   k    = 0;
#pragma unroll
        for (int jj = 0; jj < 4; jj++) {
            const int j = c * 4 + jj;
            if ((mkb >> j) & 1u) {
                prod *= (e[j] + Aexcl);
                gs   += g[j];
                k++;
            }
        }
        ll += gs - (float)k * M - __logf(prod);     // k==0: gs=0, log(1)=0 -> 0
    }

    // ---- warp reduce ll + any-valid ----
    const unsigned anyb = __ballot_sync(0xffffffffu, mkb != 0u);
#pragma unroll
    for (int off = 16; off; off >>= 1)
        ll += __shfl_xor_sync(0xffffffffu, ll, off);
    if (lane == 0) {
        g_row_ll[row]   = ll;
        g_row_used[row] = (anyb != 0u) ? 1u : 0u;
    }

    // ---- grid completion: one atomic per block (256 total) ----
    __shared__ unsigned is_last;
    __syncthreads();
    if (t == 0) {
        __threadfence();                            // publish this block's rows
        unsigned prev = atomicAdd(&g_done_count, 1u);
        is_last = (prev == GRID - 1) ? 1u : 0u;
    }
    __syncthreads();

    // ---- last block: deterministic final reduction over all rows ----
    if (is_last) {
        float sum = 0.0f;
        int   cnt = 0;
#pragma unroll
        for (int i = t; i < BB; i += TPB) {         // fixed order -> deterministic
            unsigned u = __ldcg(&g_row_used[i]);
            float    r = __ldcg(&g_row_ll[i]);
            if (u) { sum += r; cnt++; }
        }
#pragma unroll
        for (int off = 16; off; off >>= 1) {
            sum += __shfl_xor_sync(0xffffffffu, sum, off);
            cnt += __shfl_xor_sync(0xffffffffu, cnt, off);
        }
        __shared__ float fsum[WPB];
        __shared__ int   fcnt[WPB];
        if (lane == 0) { fsum[w] = sum; fcnt[w] = cnt; }
        __syncthreads();
        if (t == 0) {
            float S = 0.0f; int C = 0;
#pragma unroll
            for (int i = 0; i < WPB; i++) { S += fsum[i]; C += fcnt[i]; }
            out[0] = (C > 0) ? (-S / (float)C) : 0.0f;
            g_done_count = 0;                       // reset for next replay
        }
    }
}

extern "C" void kernel_launch(void* const* d_in, const int* in_sizes, int n_in,
                              void* d_out, int out_size)
{
    const float* s    = (const float*)d_in[0];   // [B, N] float32
    const int*   seqs = (const int*)d_in[1];     // [B, L] int32
    float*       out  = (float*)d_out;           // [1] float32

    listnet_warp_kernel<<<GRID, TPB>>>(s, seqs, out);
}

// round 7
// speedup vs baseline: 1.5923x; 1.0327x over previous
#include <cuda_runtime.h>
#include <cuda_bf16.h>

// Fixed shapes from reference setup_inputs
#define BB 2048
#define NN 8192
#define LL 512
#define NEGBIG (-1e30f)
#define TPB 256
#define WPR 4               // warps per row
#define RPB 2               // rows per block (TPB/32/WPR)
#define GRID (BB / RPB)     // 1024 blocks
#define EPL 4               // elements per lane (LL / (32*WPR))

// Scratch (allocation-free)
__device__ float    g_row_ll[BB];
__device__ unsigned g_row_used[BB];
__device__ unsigned g_done_count = 0;   // returns to 0 each launch

__global__ __launch_bounds__(TPB) void listnet_warp4_kernel(
    const float* __restrict__ s, const int* __restrict__ seqs,
    float* __restrict__ out)
{
    __shared__ float    smax[8];    // per-warp max
    __shared__ float    stot[8];    // per-warp exp-sum total
    __shared__ float    sll[8];     // per-warp ll partial
    __shared__ unsigned sany[8];    // per-warp any-valid
    __shared__ unsigned is_last;

    const int t    = threadIdx.x;
    const int lane = t & 31;
    const int wid  = t >> 5;            // 0..7
    const int rin  = wid >> 2;          // row within block: 0..1
    const int wr   = wid & 3;           // warp within row: 0..3
    const int row  = blockIdx.x * RPB + rin;

    const float* __restrict__ srow = s + (size_t)row * NN;
    // this lane's 4 contiguous elements of the row
    const int ebase = wr * (32 * EPL) + lane * EPL;

    // ---- coalesced int4 index load ----
    const int4 vi = *(const int4*)(seqs + (size_t)row * LL + ebase);
    int v[EPL] = {vi.x, vi.y, vi.z, vi.w};

    // ---- predicated gathers + sanitize; g = gm (NEGBIG when masked) ----
    float    g[EPL];
    unsigned mkb = 0u;
#pragma unroll
    for (int j = 0; j < EPL; j++) {
        const int  vv = v[j];
        const bool mk = (vv != -1);
        float x = NEGBIG;
        if (mk) {
            int idx = vv < 0 ? 0 : (vv > (NN - 1) ? (NN - 1) : vv);
            x = __ldg(srow + idx);
            x = fminf(fmaxf(x, -1e6f), 1e6f);       // inf -> +/-1e6
            x = (x != x) ? 0.0f : x;                // nan -> 0
        }
        g[j] = x;
        mkb |= (mk ? 1u : 0u) << j;
    }

    // ---- warp max -> smem ----
    float mx = fmaxf(fmaxf(g[0], g[1]), fmaxf(g[2], g[3]));
#pragma unroll
    for (int off = 16; off; off >>= 1)
        mx = fmaxf(mx, __shfl_xor_sync(0xffffffffu, mx, off));
    const unsigned anyb = __ballot_sync(0xffffffffu, mkb != 0u);
    if (lane == 0) { smax[wid] = mx; sany[wid] = anyb; }
    __syncthreads();

    // row max over this row's 4 warps
    const int wb = rin * WPR;
    const float M = fmaxf(fmaxf(smax[wb+0], smax[wb+1]),
                          fmaxf(smax[wb+2], smax[wb+3]));

    // ---- exp (masked -> 0 automatically) ----
    float e[EPL];
#pragma unroll
    for (int j = 0; j < EPL; j++) e[j] = __expf(g[j] - M);

    // ---- intra-lane suffix sum: e[j] := sum_{l>=j within lane} ----
#pragma unroll
    for (int j = EPL - 2; j >= 0; j--) e[j] += e[j + 1];

    // ---- warp inclusive-suffix scan of lane totals ----
    float incl = e[0];
#pragma unroll
    for (int off = 1; off < 32; off <<= 1) {
        float o = __shfl_down_sync(0xffffffffu, incl, off);
        if (lane + off < 32) incl += o;
    }
    // publish warp total (lane0's incl)
    if (lane == 0) stot[wid] = incl;
    __syncthreads();

    // carry from warps covering later elements of this row
    float after = 0.0f;
#pragma unroll
    for (int w2 = 0; w2 < WPR; w2++)
        if (w2 > wr) after += stot[wb + w2];

    float Aexcl = __shfl_down_sync(0xffffffffu, incl, 1);   // higher lanes' suffix
    if (lane == 31) Aexcl = 0.0f;
    const float carry = Aexcl + after;

    // ---- batched log: ONE __logf per lane (product of 4 suffix terms) ----
    float prod = 1.0f, gs = 0.0f;
    int   k    = 0;
#pragma unroll
    for (int j = 0; j < EPL; j++) {
        if ((mkb >> j) & 1u) {
            prod *= (e[j] + carry);   // suffix_j = intra-lane suffix + carry
            gs   += g[j];
            k++;
        }
    }
    float ll = gs - (float)k * M - __logf(prod);    // k==0 -> 0

    // ---- warp reduce ll, then combine the row's 4 warps ----
#pragma unroll
    for (int off = 16; off; off >>= 1)
        ll += __shfl_xor_sync(0xffffffffu, ll, off);
    if (lane == 0) sll[wid] = ll;
    __syncthreads();

    if (wr == 0 && lane == 0) {
        float rll = (sll[wb+0] + sll[wb+1]) + (sll[wb+2] + sll[wb+3]);
        unsigned ru = sany[wb+0] | sany[wb+1] | sany[wb+2] | sany[wb+3];
        g_row_ll[row]   = rll;
        g_row_used[row] = ru ? 1u : 0u;
    }

    // ---- grid completion: one atomic per block ----
    __syncthreads();
    if (t == 0) {
        __threadfence();
        unsigned prev = atomicAdd(&g_done_count, 1u);
        is_last = (prev == GRID - 1) ? 1u : 0u;
    }
    __syncthreads();

    // ---- last block: deterministic final reduction over all rows ----
    if (is_last) {
        float sum = 0.0f;
        int   cnt = 0;
#pragma unroll
        for (int i = t; i < BB; i += TPB) {
            unsigned u = __ldcg(&g_row_used[i]);
            float    r = __ldcg(&g_row_ll[i]);
            if (u) { sum += r; cnt++; }
        }
#pragma unroll
        for (int off = 16; off; off >>= 1) {
            sum += __shfl_xor_sync(0xffffffffu, sum, off);
            cnt += __shfl_xor_sync(0xffffffffu, cnt, off);
        }
        __shared__ float fsum[8];
        __shared__ int   fcnt[8];
        if (lane == 0) { fsum[wid] = sum; fcnt[wid] = cnt; }
        __syncthreads();
        if (t == 0) {
            float S = 0.0f; int C = 0;
#pragma unroll
            for (int i = 0; i < 8; i++) { S += fsum[i]; C += fcnt[i]; }
            out[0] = (C > 0) ? (-S / (float)C) : 0.0f;
            g_done_count = 0;                       // reset for next replay
        }
    }
}

extern "C" void kernel_launch(void* const* d_in, const int* in_sizes, int n_in,
                              void* d_out, int out_size)
{
    const float* s    = (const float*)d_in[0];   // [B, N] float32
    const int*   seqs = (const int*)d_in[1];     // [B, L] int32
    float*       out  = (float*)d_out;           // [1] float32

    listnet_warp4_kernel<<<GRID, TPB>>>(s, seqs, out);
}